// round 2
// baseline (speedup 1.0000x reference)
#include <cuda_runtime.h>
#include <math.h>

#define TPIf 6.2831853071795864769f

constexpr int Bsz  = 16384;
constexpr int CINc = 48;
constexpr int S    = 15;
constexpr int MID  = 240;
constexpr int EMB  = 6;
constexpr int OUTC = 48;
constexpr int BT   = 4;     // samples per CTA
constexpr int NT   = 256;   // threads per CTA

constexpr int XROW   = 36;            // padded x row stride (floats), 16B aligned
constexpr int XPANEL = 24*XROW + 4;   // 868 floats, !=0 mod 32 -> bank skew
constexpr int WBUF_F = 32*720;        // 23040 floats (30 rows used + overrun slack)

struct Smem {
    float xpad[8*XPANEL];        // 6944  : 8 panels = (b,chalf) x 24 rows x 36
    float h1[BT*MID*S];          // 14400 : [b][m][s]
    float wbuf[WBUF_F];          // 23040 : staged weights (all stages reuse)
    float h2[BT*EMB*S];          // 360
    float sigp[BT*EMB*XROW];     // 864   : padded sinusoid rows
    float red2[192*15];          // 2880  : partial-sum scratch
    float redsum[4][64];
    float redsq[4][64];
    float ctab[15], stab[15];
    float mean[BT], rstd[BT];
    float outsm[BT*OUTC];        // 192
};

__global__ void __launch_bounds__(NT, 1)
pae_kernel(const float* __restrict__ x,
           const float* __restrict__ w1,  const float* __restrict__ b1,
           const float* __restrict__ nw1, const float* __restrict__ nb1,
           const float* __restrict__ w2,  const float* __restrict__ b2,
           const float* __restrict__ fcw, const float* __restrict__ fcb,
           const float* __restrict__ dw1, const float* __restrict__ db1,
           const float* __restrict__ dnw, const float* __restrict__ dnb,
           const float* __restrict__ dw2, const float* __restrict__ db2,
           float* __restrict__ out)
{
    extern __shared__ float sm_raw[];
    Smem& sm = *reinterpret_cast<Smem*>(sm_raw);
    const int t  = threadIdx.x;
    const int b0 = blockIdx.x * BT;

    // ---------------- phase 0: zero pads, twiddle tables ----------------
    for (int i = t; i < 8*XPANEL; i += NT) sm.xpad[i] = 0.f;
    for (int i = t; i < BT*EMB*XROW; i += NT) sm.sigp[i] = 0.f;
    if (t < 15) {
        float s_, c_;
        sincosf(TPIf * (float)t / 15.f, &s_, &c_);
        sm.ctab[t] = c_;
        sm.stab[t] = -s_;   // exp(-i*2pi*t/15) imaginary part
    }
    __syncthreads();

    // load x[b0..b0+3] into padded, panel-skewed smem layout
    for (int i = t; i < BT*720; i += NT) {
        int b = i / 720, r = i - b*720;
        int c = r / 15,  s = r - c*15;
        int panel = b*2 + (c >= 24);
        int row   = (c >= 24) ? c - 24 : c;
        sm.xpad[panel*XPANEL + row*XROW + 7 + s] = x[(size_t)(b0+b)*720 + r];
    }

    // ---------------- phase 1: conv1 (48->240, K=15, same pad) ----------------
    const int bb = t & 3;
    const int ch = (t >> 2) & 1;
    const int ml = t >> 3;
    float lsum = 0.f, lsq = 0.f;

    for (int chunk = 0; chunk < 8; ++chunk) {
        __syncthreads();
        {   // stage 30 output channels of conv1_w: 30*720 floats
            const float4* src = (const float4*)(w1 + (size_t)chunk*30*720);
            float4* dst = (float4*)sm.wbuf;
            for (int i = t; i < 30*180; i += NT) dst[i] = src[i];
        }
        __syncthreads();

        float acc[15];
        #pragma unroll
        for (int s = 0; s < 15; ++s) acc[s] = 0.f;

        const float* wrow = sm.wbuf + ml*720 + ch*360;           // (may read slack rows for t>=240)
        const float* xr   = sm.xpad + (bb*2 + ch)*XPANEL;

        #pragma unroll 1
        for (int c = 0; c < 24; ++c) {
            float xv[32];
            const float4* xp = (const float4*)(xr + c*XROW);
            #pragma unroll
            for (int q = 0; q < 8; ++q) {
                float4 v = xp[q];
                xv[4*q+0]=v.x; xv[4*q+1]=v.y; xv[4*q+2]=v.z; xv[4*q+3]=v.w;
            }
            const float* wr = wrow + c*15;
            #pragma unroll
            for (int k = 0; k < 15; ++k) {
                float w = wr[k];
                #pragma unroll
                for (int s = 0; s < 15; ++s) acc[s] = fmaf(w, xv[k+s], acc[s]);
            }
        }
        // combine the two c-halves (partner = lane ^ 4, same warp)
        #pragma unroll
        for (int s = 0; s < 15; ++s) acc[s] += __shfl_xor_sync(0xffffffffu, acc[s], 4);

        if (t < 240 && ch == 0) {
            int m = chunk*30 + ml;
            float bias = b1[m];
            float* hrow = sm.h1 + bb*3600 + m*15;
            #pragma unroll
            for (int s = 0; s < 15; ++s) {
                float v = acc[s] + bias;
                hrow[s] = v;
                lsum += v; lsq += v*v;
            }
        }
    }
    // deterministic LN1 reduction
    if (t < 240 && ch == 0) { sm.redsum[bb][ml] = lsum; sm.redsq[bb][ml] = lsq; }
    __syncthreads();
    if (t < BT) {
        float s_ = 0.f, q_ = 0.f;
        for (int i = 0; i < 30; ++i) { s_ += sm.redsum[t][i]; q_ += sm.redsq[t][i]; }
        float mn  = s_ * (1.f/3600.f);
        float var = q_ * (1.f/3600.f) - mn*mn;
        sm.mean[t] = mn;
        sm.rstd[t] = rsqrtf(var + 1e-5f);
    }
    __syncthreads();

    // ---------------- phase 2: LN1 + ELU (in place) ----------------
    for (int i = t; i < BT*3600; i += NT) {
        int b = i / 3600, r = i - b*3600;
        float v = sm.h1[i];
        v = (v - sm.mean[b]) * sm.rstd[b] * nw1[r] + nb1[r];
        sm.h1[i] = (v > 0.f) ? v : expm1f(v);
    }
    __syncthreads();

    // ---------------- phase 3: stage conv2_w (6*240*15 = 21600 floats) ----------------
    {
        const float4* src = (const float4*)w2;
        float4* dst = (float4*)sm.wbuf;
        for (int i = t; i < 5400; i += NT) dst[i] = src[i];
    }
    __syncthreads();

    // ---------------- phase 4: conv2 (240->6) : tasks (e,b,cgroup) ----------------
    if (t < 192) {
        int b = t & 3, cg = (t >> 2) & 7, e = t >> 5;
        float acc[15];
        #pragma unroll
        for (int s = 0; s < 15; ++s) acc[s] = 0.f;
        const float* hbase = sm.h1 + b*3600;
        #pragma unroll 1
        for (int ci = 0; ci < 30; ++ci) {
            int c = cg*30 + ci;
            float xv[32];
            #pragma unroll
            for (int j = 0; j < 32; ++j)
                xv[j] = (j >= 7 && j < 22) ? hbase[c*15 + j - 7] : 0.f;
            const float* wr = sm.wbuf + e*3600 + c*15;
            #pragma unroll
            for (int k = 0; k < 15; ++k) {
                float w = wr[k];
                #pragma unroll
                for (int s = 0; s < 15; ++s) acc[s] = fmaf(w, xv[k+s], acc[s]);
            }
        }
        #pragma unroll
        for (int s = 0; s < 15; ++s) sm.red2[t*15 + s] = acc[s];
    }
    __syncthreads();
    // reduce c-groups into h2 (+ bias), deterministic
    for (int i = t; i < 360; i += NT) {
        int be = i / 15, s = i - be*15;
        int e = be >> 2, b = be & 3;
        float v = b2[e];
        #pragma unroll
        for (int cg = 0; cg < 8; ++cg) v += sm.red2[(e*32 + cg*4 + b)*15 + s];
        sm.h2[(b*EMB + e)*15 + s] = v;
    }
    __syncthreads();

    // ---------------- phase 5: DFT stats + fc/atan2 + sinusoid ----------------
    if (t < 24) {
        int b = t & 3, e = t >> 2;
        const float* hr = sm.h2 + (b*EMB + e)*15;
        float h[15];
        #pragma unroll
        for (int s = 0; s < 15; ++s) h[s] = hr[s];

        float re0 = 0.f;
        #pragma unroll
        for (int s = 0; s < 15; ++s) re0 += h[s];

        float psum = 0.f, fs = 0.f;
        for (int j = 1; j <= 7; ++j) {
            float re = 0.f, im = 0.f;
            int idx = 0;
            #pragma unroll
            for (int s = 0; s < 15; ++s) {
                re = fmaf(h[s], sm.ctab[idx], re);
                im = fmaf(h[s], sm.stab[idx], im);
                idx += j; if (idx >= 15) idx -= 15;
            }
            float pw = re*re + im*im;
            psum += pw;
            fs   += (float)j * pw;
        }
        float f   = fs / (0.3f * psum);          // freqs[j] = j/0.3
        float a   = 2.f * sqrtf(psum) * (1.f/15.f);
        float off = re0 * (1.f/15.f);

        float v0 = fcb[e*2 + 0], v1 = fcb[e*2 + 1];
        #pragma unroll
        for (int s = 0; s < 15; ++s) {
            v0 = fmaf(h[s], fcw[e*30 + s],      v0);
            v1 = fmaf(h[s], fcw[e*30 + 15 + s], v1);
        }
        float p = atan2f(v1, v0) * (1.f/TPIf);

        float* srow = sm.sigp + (b*EMB + e)*XROW;
        #pragma unroll
        for (int s = 0; s < 15; ++s) {
            float arg = -0.15f + (float)s * (0.3f/14.f);
            srow[7 + s] = fmaf(a, sinf(TPIf * (f*arg + p)), off);
        }
    }
    __syncthreads();

    // ---------------- phase 6: stage deconv1_w (240*6*15 = 21600) ----------------
    {
        const float4* src = (const float4*)dw1;
        float4* dst = (float4*)sm.wbuf;
        for (int i = t; i < 5400; i += NT) dst[i] = src[i];
    }
    __syncthreads();

    // ---------------- phase 7: deconv1 (6->240) ----------------
    lsum = 0.f; lsq = 0.f;
    {
        int b = t & 3;
        const float* sp = sm.sigp + b*EMB*XROW;
        for (int task = t; task < 960; task += NT) {
            int m = task >> 2;
            float acc[15];
            #pragma unroll
            for (int s = 0; s < 15; ++s) acc[s] = 0.f;
            #pragma unroll 1
            for (int e = 0; e < 6; ++e) {
                float xv[32];
                const float4* xp = (const float4*)(sp + e*XROW);
                #pragma unroll
                for (int q = 0; q < 8; ++q) {
                    float4 v = xp[q];
                    xv[4*q+0]=v.x; xv[4*q+1]=v.y; xv[4*q+2]=v.z; xv[4*q+3]=v.w;
                }
                const float* wr = sm.wbuf + m*90 + e*15;
                #pragma unroll
                for (int k = 0; k < 15; ++k) {
                    float w = wr[k];
                    #pragma unroll
                    for (int s = 0; s < 15; ++s) acc[s] = fmaf(w, xv[k+s], acc[s]);
                }
            }
            float bias = db1[m];
            float* hrow = sm.h1 + b*3600 + m*15;
            #pragma unroll
            for (int s = 0; s < 15; ++s) {
                float v = acc[s] + bias;
                hrow[s] = v;
                lsum += v; lsq += v*v;
            }
        }
    }
    sm.redsum[t & 3][t >> 2] = lsum;
    sm.redsq [t & 3][t >> 2] = lsq;
    __syncthreads();
    if (t < BT) {
        float s_ = 0.f, q_ = 0.f;
        for (int i = 0; i < 64; ++i) { s_ += sm.redsum[t][i]; q_ += sm.redsq[t][i]; }
        float mn  = s_ * (1.f/3600.f);
        float var = q_ * (1.f/3600.f) - mn*mn;
        sm.mean[t] = mn;
        sm.rstd[t] = rsqrtf(var + 1e-5f);
    }
    __syncthreads();

    // ---------------- phase 8: LN2 + ELU ----------------
    for (int i = t; i < BT*3600; i += NT) {
        int b = i / 3600, r = i - b*3600;
        float v = sm.h1[i];
        v = (v - sm.mean[b]) * sm.rstd[b] * dnw[r] + dnb[r];
        sm.h1[i] = (v > 0.f) ? v : expm1f(v);
    }
    __syncthreads();
    if (t < BT*OUTC) sm.outsm[t] = db2[t % OUTC];   // init with bias

    // ---------------- phase 9: deconv2, only s = 14 (k in [0,7], positions 7..14) ----------------
    // 48 output channels staged 6 at a time -> 8 chunks (was 6: BUG fixed)
    for (int chunk = 0; chunk < 8; ++chunk) {
        __syncthreads();
        {   // stage 6 output rows: 6*3600 = 21600 floats
            const float4* src = (const float4*)(dw2 + (size_t)chunk*6*3600);
            float4* dst = (float4*)sm.wbuf;
            for (int i = t; i < 5400; i += NT) dst[i] = src[i];
        }
        __syncthreads();
        if (t < 192) {
            int b = t & 3, cg = (t >> 2) & 7, ol = t >> 5;
            float acc = 0.f;
            const float* hbase = sm.h1 + b*3600;
            const float* wb = sm.wbuf + ol*3600;
            #pragma unroll 1
            for (int ci = 0; ci < 30; ++ci) {
                int c = cg*30 + ci;
                const float* hr = hbase + c*15 + 7;
                const float* wr = wb + c*15;
                #pragma unroll
                for (int k = 0; k < 8; ++k) acc = fmaf(hr[k], wr[k], acc);
            }
            sm.red2[t] = acc;
        }
        __syncthreads();
        if (t < 24) {
            int b = t & 3, ol = t >> 2;
            int o = chunk*6 + ol;
            float v = 0.f;
            #pragma unroll
            for (int cg = 0; cg < 8; ++cg) v += sm.red2[ol*32 + cg*4 + b];
            sm.outsm[b*OUTC + o] += v;
        }
    }
    __syncthreads();

    // ---------------- output ----------------
    if (t < BT*OUTC) {
        int b = t / OUTC, o = t - b*OUTC;
        out[(size_t)(b0 + b)*OUTC + o] = sm.outsm[t];
    }
}

extern "C" void kernel_launch(void* const* d_in, const int* in_sizes, int n_in,
                              void* d_out, int out_size)
{
    const float* x   = (const float*)d_in[0];
    const float* w1  = (const float*)d_in[1];
    const float* b1  = (const float*)d_in[2];
    const float* nw1 = (const float*)d_in[3];
    const float* nb1 = (const float*)d_in[4];
    const float* w2  = (const float*)d_in[5];
    const float* b2  = (const float*)d_in[6];
    const float* fcw = (const float*)d_in[7];
    const float* fcb = (const float*)d_in[8];
    const float* dw1 = (const float*)d_in[9];
    const float* db1 = (const float*)d_in[10];
    const float* dnw = (const float*)d_in[11];
    const float* dnb = (const float*)d_in[12];
    const float* dw2 = (const float*)d_in[13];
    const float* db2 = (const float*)d_in[14];
    float* out = (float*)d_out;

    cudaFuncSetAttribute(pae_kernel, cudaFuncAttributeMaxDynamicSharedMemorySize,
                         (int)sizeof(Smem));
    pae_kernel<<<Bsz / BT, NT, sizeof(Smem)>>>(x, w1, b1, nw1, nb1, w2, b2,
                                               fcw, fcb, dw1, db1, dnw, dnb,
                                               dw2, db2, out);
}